// round 12
// baseline (speedup 1.0000x reference)
#include <cuda_runtime.h>
#include <math.h>

#define B 8
#define L 2048
#define NT 21          // num types incl. padding idx 0
#define DTY 32
#define DH 544         // 512 + 32
#define THREADS 256
#define NBLK (148 * 6)           // exactly one persistent wave (regs<=40 -> 6/SM)
#define TPB 512                   // tiles per batch: 256 row-groups x 2 j-halves
#define NTILES (B * TPB)          // 4096

// ---------------------------------------------------------------------------
// Persistent fused kernel, one wave of 888 blocks (6/SM, never oversubscribed).
// Tile = 8 mirrored rows {4q..4q+3} u {L-4-4q..L-1-4q} x one 1024-col j-half:
// equal cost everywhere (mirror pairing balances the triangle exp work).
// j-side LDS loads are shared across all 8 rows (R7 reuse preserved).
// Static batch-major tile assignment: s_t/s_ty reload at most twice a block;
// the 441-entry type-pair table is batch-independent, built once per block.
// ---------------------------------------------------------------------------
__global__ __launch_bounds__(THREADS, 6) void fused_kernel(
    const int*   __restrict__ event_type,
    const float* __restrict__ event_time,
    const float* __restrict__ Wt_pos,
    const float* __restrict__ type_emb,
    const float* __restrict__ w_l, const float* __restrict__ b_l,
    const float* __restrict__ w_g, const float* __restrict__ b_g,
    float* __restrict__ scores,
    float* __restrict__ hidden,
    float* __restrict__ tdiff) {

    __shared__ float          s_t[L];
    __shared__ unsigned char  s_ty[L];
    __shared__ float2         s_tab[NT * NT];   // {0.4*g, 1/l}
    __shared__ float          pa[NT], pb[NT], ga[NT], gb[NT];

    const int tid = threadIdx.x;

    // --- one-time: per-type dot products + 441-entry table (batch-indep) ----
    if (tid < NT) {
        float sa = 0.f, sb = 0.f, sga = 0.f, sgb = 0.f;
#pragma unroll
        for (int k = 0; k < DTY; k++) {
            float e = type_emb[tid * DTY + k];
            sa  = fmaf(e, w_l[k],       sa);
            sb  = fmaf(e, w_l[DTY + k], sb);
            sga = fmaf(e, w_g[k],       sga);
            sgb = fmaf(e, w_g[DTY + k], sgb);
        }
        pa[tid] = sa; pb[tid] = sb; ga[tid] = sga; gb[tid] = sgb;
    }
    __syncthreads();
    {
        const float blv = b_l[0], bgv = b_g[0];
        for (int idx = tid; idx < NT * NT; idx += THREADS) {
            int ti = idx / NT;   // i-side type
            int tj = idx % NT;   // j-side type
            float xl = pa[tj] + pb[ti] + blv;
            float sp = fmaxf(xl, 0.f) + log1pf(expf(-fabsf(xl)));
            float lv = sp + 1e-6f;
            float xg = 5.0f * (ga[tj] + gb[ti] + bgv);
            float g  = 1.f / (1.f + expf(-xg));
            s_tab[idx] = make_float2(0.4f * g, 1.f / lv);
        }
    }

    // per-thread hidden constants
    const float c   = (float)(-9.210340371976184 / 512.0); // -ln(10000)/d_model
    const float div = expf((float)(2 * tid) * c);
    const float wt  = Wt_pos[tid];

    const int p  = blockIdx.x;
    const int t0 = (int)(((long long)p       * NTILES) / NBLK);
    const int t1 = (int)(((long long)(p + 1) * NTILES) / NBLK);
    int cur_b = -1;

    for (int t = t0; t < t1; ++t) {
        const int b    = t / TPB;
        const int r    = t - b * TPB;
        const int q    = r >> 1;         // row-group 0..255
        const int half = r & 1;          // j-half
        if (b != cur_b) {
            __syncthreads();             // retire reads of previous batch rows
            for (int j = tid; j < L; j += THREADS) {
                s_t[j]  = event_time[b * L + j];
                s_ty[j] = (unsigned char)event_type[b * L + j];
            }
            __syncthreads();
            cur_b = b;
        }
        const int q4  = q * 4;
        const int mir = L - 4 - q4;

        // --- hidden rows (once per row-group, on the half==0 tile) ----------
        if (half == 0) {
#pragma unroll
            for (int ii = 0; ii < 8; ii++) {
                int   i    = (ii < 4) ? (q4 + ii) : (mir + ii - 4);
                float s, cth;
                sincosf((float)i * div + s_t[i] * wt, &s, &cth);
                float* base = hidden + ((size_t)(cur_b * L + i)) * DH;
                __stcs(base + tid,       s);
                __stcs(base + 256 + tid, cth);
            }
            int row = tid >> 5;
            int col = tid & 31;
            int i   = (row < 4) ? (q4 + row) : (mir + row - 4);
            int ty  = (int)s_ty[i];
            __stcs(hidden + ((size_t)(cur_b * L + i)) * DH + 512 + col,
                   type_emb[ty * DTY + col]);
        }

        // --- pairwise: 8 rows x one 1024-col j-half (single chunk) ----------
        float ti_r[8];
        int   tb_r[8];
#pragma unroll
        for (int ii = 0; ii < 8; ii++) {
            int i = (ii < 4) ? (q4 + ii) : (mir + ii - 4);
            ti_r[ii] = s_t[i];
            tb_r[ii] = (int)s_ty[i] * NT;
        }
        float* sc0 = scores + ((size_t)(cur_b * L + q4))  * L;
        float* td0 = tdiff  + ((size_t)(cur_b * L + q4))  * L;
        float* sc1 = scores + ((size_t)(cur_b * L + mir)) * L;
        float* td1 = tdiff  + ((size_t)(cur_b * L + mir)) * L;

        const int j = half * 1024 + tid * 4;
        const float4 tj  = *reinterpret_cast<const float4*>(&s_t[j]);
        const uchar4 tyv = *reinterpret_cast<const uchar4*>(&s_ty[j]);
        const int jx = tyv.x, jy = tyv.y, jz = tyv.z, jw = tyv.w;

#pragma unroll
        for (int ii = 0; ii < 8; ii++) {
            const int   i  = (ii < 4) ? (q4 + ii) : (mir + ii - 4);
            const float ti = ti_r[ii];
            float4 dv;
            dv.x = fabsf(ti - tj.x);
            dv.y = fabsf(ti - tj.y);
            dv.z = fabsf(ti - tj.z);
            dv.w = fabsf(ti - tj.w);

            float4 sv = make_float4(0.f, 0.f, 0.f, 0.f);
            if (j < i) {
                const int tb = tb_r[ii];
                float2 v; float e, se, ex;
                v = s_tab[tb + jx]; e = dv.x * v.y;
                se = __expf(-0.5f * e * e); ex = __expf(-e);
                sv.x = v.x * fmaf(0.75f, ex, se);
                v = s_tab[tb + jy]; e = dv.y * v.y;
                se = __expf(-0.5f * e * e); ex = __expf(-e);
                sv.y = (j + 1 < i) ? v.x * fmaf(0.75f, ex, se) : 0.f;
                v = s_tab[tb + jz]; e = dv.z * v.y;
                se = __expf(-0.5f * e * e); ex = __expf(-e);
                sv.z = (j + 2 < i) ? v.x * fmaf(0.75f, ex, se) : 0.f;
                v = s_tab[tb + jw]; e = dv.w * v.y;
                se = __expf(-0.5f * e * e); ex = __expf(-e);
                sv.w = (j + 3 < i) ? v.x * fmaf(0.75f, ex, se) : 0.f;
            }
            float* sc = (ii < 4) ? (sc0 + (size_t)ii * L) : (sc1 + (size_t)(ii - 4) * L);
            float* td = (ii < 4) ? (td0 + (size_t)ii * L) : (td1 + (size_t)(ii - 4) * L);
            __stcs(reinterpret_cast<float4*>(sc + j), sv);
            __stcs(reinterpret_cast<float4*>(td + j), dv);
        }
    }
}

// ---------------------------------------------------------------------------
extern "C" void kernel_launch(void* const* d_in, const int* in_sizes, int n_in,
                              void* d_out, int out_size) {
    const int*   event_type = (const int*)d_in[0];
    const float* event_time = (const float*)d_in[1];
    // d_in[2] = arrival_times (unused by reference)
    const float* Wt_pos   = (const float*)d_in[3];
    const float* type_emb = (const float*)d_in[4];
    const float* w_l      = (const float*)d_in[5];
    const float* b_l      = (const float*)d_in[6];
    const float* w_g      = (const float*)d_in[7];
    const float* b_g      = (const float*)d_in[8];

    float* out    = (float*)d_out;
    float* scores = out;                                   // [B, L, L]
    float* hidden = out + (size_t)B * L * L;               // [B, L, 544]
    float* tdiff  = hidden + (size_t)B * L * DH;           // [B, L, L]

    fused_kernel<<<NBLK, THREADS>>>(
        event_type, event_time, Wt_pos, type_emb,
        w_l, b_l, w_g, b_g, scores, hidden, tdiff);
}

// round 13
// speedup vs baseline: 1.3240x; 1.3240x over previous
#include <cuda_runtime.h>
#include <math.h>

#define B 8
#define L 2048
#define NT 21          // num types incl. padding idx 0
#define DTY 32
#define DH 544         // 512 + 32
#define THREADS 256
#define QPB 512        // 4-row mirrored tiles per batch
// grid = B * QPB = 4096 blocks, flat launch (no persistence)

// ---------------------------------------------------------------------------
// Flat-launch fused kernel (R7 structure, finer tiles, full occupancy).
// Block (b, q) owns 4 mirrored rows {2q, 2q+1} u {L-2-2q, L-1-2q}: every
// block performs exactly the same lower-triangle exp/table work, and the
// halved block duration shrinks the final-wave tail. __launch_bounds__(.,8)
// caps regs at 32 -> 8 blocks/SM = 64 warps (full occupancy).
// ---------------------------------------------------------------------------
__global__ __launch_bounds__(THREADS, 8) void fused_kernel(
    const int*   __restrict__ event_type,
    const float* __restrict__ event_time,
    const float* __restrict__ Wt_pos,
    const float* __restrict__ type_emb,
    const float* __restrict__ w_l, const float* __restrict__ b_l,
    const float* __restrict__ w_g, const float* __restrict__ b_g,
    float* __restrict__ scores,
    float* __restrict__ hidden,
    float* __restrict__ tdiff) {

    __shared__ float          s_t[L];
    __shared__ unsigned char  s_ty[L];
    __shared__ float2         s_tab[NT * NT];   // {0.4*g, 1/l}
    __shared__ float          pa[NT], pb[NT], ga[NT], gb[NT];

    const int tid = threadIdx.x;
    const int blk = blockIdx.x;
    const int b   = blk >> 9;            // blk / QPB
    const int q   = blk & (QPB - 1);     // blk % QPB
    const int i0  = 2 * q;               // rows i0, i0+1
    const int m0  = L - 2 - 2 * q;       // rows m0, m0+1

    // --- stage 1: row loads + per-type dot products -------------------------
    for (int j = tid; j < L; j += THREADS) {
        s_t[j]  = event_time[b * L + j];
        s_ty[j] = (unsigned char)event_type[b * L + j];
    }
    if (tid < NT) {
        float sa = 0.f, sb = 0.f, sga = 0.f, sgb = 0.f;
#pragma unroll
        for (int k = 0; k < DTY; k++) {
            float e = type_emb[tid * DTY + k];
            sa  = fmaf(e, w_l[k],       sa);
            sb  = fmaf(e, w_l[DTY + k], sb);
            sga = fmaf(e, w_g[k],       sga);
            sgb = fmaf(e, w_g[DTY + k], sgb);
        }
        pa[tid] = sa; pb[tid] = sb; ga[tid] = sga; gb[tid] = sgb;
    }
    __syncthreads();

    // --- stage 2: build 441-entry float2 table ------------------------------
    {
        const float blv = b_l[0], bgv = b_g[0];
        for (int idx = tid; idx < NT * NT; idx += THREADS) {
            int ti = idx / NT;   // i-side type
            int tj = idx % NT;   // j-side type
            float xl = pa[tj] + pb[ti] + blv;
            float sp = fmaxf(xl, 0.f) + log1pf(expf(-fabsf(xl)));
            float lv = sp + 1e-6f;
            float xg = 5.0f * (ga[tj] + gb[ti] + bgv);
            float g  = 1.f / (1.f + expf(-xg));
            s_tab[idx] = make_float2(0.4f * g, 1.f / lv);
        }
    }

    // --- stage 3: hidden rows for the 4 mirrored positions ------------------
    {
        const float c   = (float)(-9.210340371976184 / 512.0); // -ln(10000)/d_model
        const float div = expf((float)(2 * tid) * c);
        const float wt  = Wt_pos[tid];
#pragma unroll
        for (int r = 0; r < 4; r++) {
            int   i = (r < 2) ? (i0 + r) : (m0 + r - 2);
            float s, cth;
            sincosf((float)i * div + s_t[i] * wt, &s, &cth);
            float* base = hidden + ((size_t)(b * L + i)) * DH;
            __stcs(base + tid,       s);
            __stcs(base + 256 + tid, cth);
        }
        if (tid < 128) {
            int r   = tid >> 5;          // 0..3
            int col = tid & 31;
            int i   = (r < 2) ? (i0 + r) : (m0 + r - 2);
            int ty  = (int)s_ty[i];
            __stcs(hidden + ((size_t)(b * L + i)) * DH + 512 + col,
                   type_emb[ty * DTY + col]);
        }
    }
    __syncthreads();   // s_tab / s_t complete before pairwise reads

    // --- stage 4: pairwise scores + t_diff (j-outer, 4 rows inner) ----------
    float  ti_r[4];
    int    tb_r[4];
    size_t ro_r[4];
#pragma unroll
    for (int r = 0; r < 4; r++) {
        int i = (r < 2) ? (i0 + r) : (m0 + r - 2);
        ti_r[r] = s_t[i];
        tb_r[r] = (int)s_ty[i] * NT;
        ro_r[r] = ((size_t)(b * L + i)) * L;
    }

#pragma unroll
    for (int chunk = 0; chunk < 2; ++chunk) {
        const int j = chunk * (THREADS * 4) + tid * 4;
        const float4 tj  = *reinterpret_cast<const float4*>(&s_t[j]);
        const uchar4 tyv = *reinterpret_cast<const uchar4*>(&s_ty[j]);
        const int jx = tyv.x, jy = tyv.y, jz = tyv.z, jw = tyv.w;

#pragma unroll
        for (int r = 0; r < 4; r++) {
            const int   i  = (r < 2) ? (i0 + r) : (m0 + r - 2);
            const float ti = ti_r[r];
            float4 dv;
            dv.x = fabsf(ti - tj.x);
            dv.y = fabsf(ti - tj.y);
            dv.z = fabsf(ti - tj.z);
            dv.w = fabsf(ti - tj.w);

            float4 sv = make_float4(0.f, 0.f, 0.f, 0.f);
            if (j < i) {
                const int tb = tb_r[r];
                float2 v; float e, se, ex;
                v = s_tab[tb + jx]; e = dv.x * v.y;
                se = __expf(-0.5f * e * e); ex = __expf(-e);
                sv.x = v.x * fmaf(0.75f, ex, se);
                v = s_tab[tb + jy]; e = dv.y * v.y;
                se = __expf(-0.5f * e * e); ex = __expf(-e);
                sv.y = (j + 1 < i) ? v.x * fmaf(0.75f, ex, se) : 0.f;
                v = s_tab[tb + jz]; e = dv.z * v.y;
                se = __expf(-0.5f * e * e); ex = __expf(-e);
                sv.z = (j + 2 < i) ? v.x * fmaf(0.75f, ex, se) : 0.f;
                v = s_tab[tb + jw]; e = dv.w * v.y;
                se = __expf(-0.5f * e * e); ex = __expf(-e);
                sv.w = (j + 3 < i) ? v.x * fmaf(0.75f, ex, se) : 0.f;
            }
            __stcs(reinterpret_cast<float4*>(scores + ro_r[r] + j), sv);
            __stcs(reinterpret_cast<float4*>(tdiff  + ro_r[r] + j), dv);
        }
    }
}

// ---------------------------------------------------------------------------
extern "C" void kernel_launch(void* const* d_in, const int* in_sizes, int n_in,
                              void* d_out, int out_size) {
    const int*   event_type = (const int*)d_in[0];
    const float* event_time = (const float*)d_in[1];
    // d_in[2] = arrival_times (unused by reference)
    const float* Wt_pos   = (const float*)d_in[3];
    const float* type_emb = (const float*)d_in[4];
    const float* w_l      = (const float*)d_in[5];
    const float* b_l      = (const float*)d_in[6];
    const float* w_g      = (const float*)d_in[7];
    const float* b_g      = (const float*)d_in[8];

    float* out    = (float*)d_out;
    float* scores = out;                                   // [B, L, L]
    float* hidden = out + (size_t)B * L * L;               // [B, L, 544]
    float* tdiff  = hidden + (size_t)B * L * DH;           // [B, L, L]

    fused_kernel<<<B * QPB, THREADS>>>(
        event_type, event_time, Wt_pos, type_emb,
        w_l, b_l, w_g, b_g, scores, hidden, tdiff);
}

// round 16
// speedup vs baseline: 1.4654x; 1.1068x over previous
#include <cuda_runtime.h>
#include <math.h>

#define B 8
#define L 2048
#define NT 21          // num types incl. padding idx 0
#define DTY 32
#define DH 544         // 512 + 32
#define THREADS 256
#define QBLK 256       // 8-row mirrored tiles per batch; grid = 2048

// ---------------------------------------------------------------------------
// R7 skeleton (best measured config: 2048 blocks, 256 thr, 6/SM) with
// instruction-count cuts: fast table build, fast range-reduced sincos for the
// positional embedding, and hoisted row offsets in the pairwise loop.
// Block q of batch b owns mirrored rows {4q..4q+3} u {L-4-4q..L-1-4q}
// (equal lower-triangle work per block). j-side LDS shared across 8 rows.
// ---------------------------------------------------------------------------
__global__ __launch_bounds__(THREADS, 6) void fused_kernel(
    const int*   __restrict__ event_type,
    const float* __restrict__ event_time,
    const float* __restrict__ Wt_pos,
    const float* __restrict__ type_emb,
    const float* __restrict__ w_l, const float* __restrict__ b_l,
    const float* __restrict__ w_g, const float* __restrict__ b_g,
    float* __restrict__ scores,
    float* __restrict__ hidden,
    float* __restrict__ tdiff) {

    __shared__ float          s_t[L];
    __shared__ unsigned char  s_ty[L];
    __shared__ float2         s_tab[NT * NT];   // {0.4*g, 1/l}
    __shared__ float          pa[NT], pb[NT], ga[NT], gb[NT];

    const int tid = threadIdx.x;
    const int blk = blockIdx.x;
    const int b   = blk >> 8;            // blk / QBLK
    const int q   = blk & (QBLK - 1);
    const int q4  = q * 4;
    const int mir = L - 4 - q4;          // base of mirrored 4-row group

    // --- stage 1: row loads + per-type dot products -------------------------
    for (int j = tid; j < L; j += THREADS) {
        s_t[j]  = event_time[b * L + j];
        s_ty[j] = (unsigned char)event_type[b * L + j];
    }
    if (tid < NT) {
        float sa = 0.f, sb = 0.f, sga = 0.f, sgb = 0.f;
#pragma unroll
        for (int k = 0; k < DTY; k++) {
            float e = type_emb[tid * DTY + k];
            sa  = fmaf(e, w_l[k],       sa);
            sb  = fmaf(e, w_l[DTY + k], sb);
            sga = fmaf(e, w_g[k],       sga);
            sgb = fmaf(e, w_g[DTY + k], sgb);
        }
        pa[tid] = sa; pb[tid] = sb; ga[tid] = sga; gb[tid] = sgb;
    }
    __syncthreads();

    // --- stage 2: build 441-entry float2 table (fast intrinsics) ------------
    {
        const float blv = b_l[0], bgv = b_g[0];
        for (int idx = tid; idx < NT * NT; idx += THREADS) {
            int ti = idx / NT;   // i-side type
            int tj = idx % NT;   // j-side type
            float xl = pa[tj] + pb[ti] + blv;
            // softplus(x) = max(x,0) + log(1 + exp(-|x|))
            float z  = __expf(-fabsf(xl));
            float sp = fmaxf(xl, 0.f) + __logf(1.f + z);
            float lv = sp + 1e-6f;
            float xg = 5.0f * (ga[tj] + gb[ti] + bgv);
            float g  = __frcp_rn(1.f + __expf(-xg));
            s_tab[idx] = make_float2(0.4f * g, __frcp_rn(lv));
        }
    }

    // --- stage 3: hidden rows (fast range-reduced sincos) -------------------
    {
        const float c   = (float)(-9.210340371976184 / 512.0); // -ln(10000)/d_model
        const float div = __expf((float)(2 * tid) * c);
        const float wt  = Wt_pos[tid];
        const float inv2pi = 0.15915494309189535f;
        const float twopi  = 6.283185307179586f;
#pragma unroll
        for (int ii = 0; ii < 8; ii++) {
            int   i = (ii < 4) ? (q4 + ii) : (mir + ii - 4);
            float x = (float)i * div + s_t[i] * wt;
            // range-reduce to [-pi, pi]; args <= ~2048 rad so fp32 fmaf
            // reduction error (~1e-4 abs) is far below the 1e-3 budget.
            float n = rintf(x * inv2pi);
            float r = fmaf(-twopi, n, x);
            float s, cth;
            __sincosf(r, &s, &cth);
            float* base = hidden + ((size_t)(b * L + i)) * DH;
            __stcs(base + tid,       s);
            __stcs(base + 256 + tid, cth);
        }
        int row = tid >> 5;
        int col = tid & 31;
        int i   = (row < 4) ? (q4 + row) : (mir + row - 4);
        int ty  = (int)s_ty[i];
        __stcs(hidden + ((size_t)(b * L + i)) * DH + 512 + col,
               type_emb[ty * DTY + col]);
    }
    __syncthreads();   // s_tab must be complete before pairwise reads

    // --- stage 4: pairwise scores + t_diff (j-outer, 8 rows inner) ----------
    float    ti_r[8];
    int      tb_r[8];
    unsigned ro_r[8];      // element offset of row start (fits 32 bits)
#pragma unroll
    for (int ii = 0; ii < 8; ii++) {
        int i = (ii < 4) ? (q4 + ii) : (mir + ii - 4);
        ti_r[ii] = s_t[i];
        tb_r[ii] = (int)s_ty[i] * NT;
        ro_r[ii] = (unsigned)(b * L + i) * (unsigned)L;
    }

#pragma unroll
    for (int chunk = 0; chunk < 2; ++chunk) {
        const int j = chunk * (THREADS * 4) + tid * 4;
        const float4 tj  = *reinterpret_cast<const float4*>(&s_t[j]);
        const uchar4 tyv = *reinterpret_cast<const uchar4*>(&s_ty[j]);
        const int jx = tyv.x, jy = tyv.y, jz = tyv.z, jw = tyv.w;

#pragma unroll
        for (int ii = 0; ii < 8; ii++) {
            const int   i  = (ii < 4) ? (q4 + ii) : (mir + ii - 4);
            const float ti = ti_r[ii];
            float4 dv;
            dv.x = fabsf(ti - tj.x);
            dv.y = fabsf(ti - tj.y);
            dv.z = fabsf(ti - tj.z);
            dv.w = fabsf(ti - tj.w);

            float4 sv = make_float4(0.f, 0.f, 0.f, 0.f);
            if (j < i) {
                const int tb = tb_r[ii];
                float2 v; float e, se, ex;
                v = s_tab[tb + jx]; e = dv.x * v.y;
                se = __expf(-0.5f * e * e); ex = __expf(-e);
                sv.x = v.x * fmaf(0.75f, ex, se);
                v = s_tab[tb + jy]; e = dv.y * v.y;
                se = __expf(-0.5f * e * e); ex = __expf(-e);
                sv.y = (j + 1 < i) ? v.x * fmaf(0.75f, ex, se) : 0.f;
                v = s_tab[tb + jz]; e = dv.z * v.y;
                se = __expf(-0.5f * e * e); ex = __expf(-e);
                sv.z = (j + 2 < i) ? v.x * fmaf(0.75f, ex, se) : 0.f;
                v = s_tab[tb + jw]; e = dv.w * v.y;
                se = __expf(-0.5f * e * e); ex = __expf(-e);
                sv.w = (j + 3 < i) ? v.x * fmaf(0.75f, ex, se) : 0.f;
            }
            __stcs(reinterpret_cast<float4*>(scores + ro_r[ii]) + (j >> 2), sv);
            __stcs(reinterpret_cast<float4*>(tdiff  + ro_r[ii]) + (j >> 2), dv);
        }
    }
}

// ---------------------------------------------------------------------------
extern "C" void kernel_launch(void* const* d_in, const int* in_sizes, int n_in,
                              void* d_out, int out_size) {
    const int*   event_type = (const int*)d_in[0];
    const float* event_time = (const float*)d_in[1];
    // d_in[2] = arrival_times (unused by reference)
    const float* Wt_pos   = (const float*)d_in[3];
    const float* type_emb = (const float*)d_in[4];
    const float* w_l      = (const float*)d_in[5];
    const float* b_l      = (const float*)d_in[6];
    const float* w_g      = (const float*)d_in[7];
    const float* b_g      = (const float*)d_in[8];

    float* out    = (float*)d_out;
    float* scores = out;                                   // [B, L, L]
    float* hidden = out + (size_t)B * L * L;               // [B, L, 544]
    float* tdiff  = hidden + (size_t)B * L * DH;           // [B, L, L]

    fused_kernel<<<B * QBLK, THREADS>>>(
        event_type, event_time, Wt_pos, type_emb,
        w_l, b_l, w_g, b_g, scores, hidden, tdiff);
}